// round 8
// baseline (speedup 1.0000x reference)
#include <cuda_runtime.h>
#include <cub/cub.cuh>

// Defeat --use_fast_math's expf -> __expf macro so expf = accurate libdevice
// __nv_expf, matching XLA's f32 exp bit-for-bit.
#ifdef expf
#undef expf
#endif

#define NB      4        // batch
#define NP      34125    // priors
#define NSEL    5000     // NMS_TOP_K
#define TOPK    750
#define NW      79       // ceil(NSEL/64)
#define CONF_T  0.05f
#define NMS_T   0.3f

#define RT      1024     // reduce block threads
#define CW      1024     // candidates per chunk
#define WPC     16       // mask words per chunk
#define NCH     5        // ceil(NSEL/CW)
#define ROWM_BYTES (CW * WPC * 8)   // 128 KB dynamic smem

// ---------------- static device scratch (no allocations allowed) ------------
__device__ unsigned long long g_keys_in [NB * NP];
__device__ unsigned int       g_vals_in [NB * NP];
__device__ unsigned long long g_keys_out[NB * NP];
__device__ unsigned int       g_vals_out[NB * NP];

__device__ float g_bx1[NB * NSEL];
__device__ float g_by1[NB * NSEL];
__device__ float g_bx2[NB * NSEL];
__device__ float g_by2[NB * NSEL];
__device__ float g_sc [NB * NSEL];

__device__ unsigned long long g_mask[(size_t)NB * NSEL * NW]; // zero-init; ~12.6 MB
__device__ unsigned char      g_temp[1u << 24];               // cub temp, 16 MB

// ---------------- helpers ----------------------------------------------------

__device__ __forceinline__ unsigned int f2sortable(float f) {
    unsigned int b = __float_as_uint(f);
    return (b & 0x80000000u) ? ~b : (b | 0x80000000u);
}
__device__ __forceinline__ float sortable2f(unsigned int u) {
    return __uint_as_float((u & 0x80000000u) ? (u & 0x7fffffffu) : ~u);
}

// ---------------- kernels ----------------------------------------------------

// 64-bit composite keys: high bits = (3-img) so one descending onesweep sort
// orders img 0 first; low 32 = monotonic map of thresholded score. Stable
// radix sort keeps ascending-index tie order == jax.lax.top_k.
__global__ void k_build(const float* __restrict__ conf) {
    int i = blockIdx.x * blockDim.x + threadIdx.x;
    if (i >= NB * NP) return;
    float c = conf[2 * i + 1];                 // class-1 score
    float s = (c > CONF_T) ? c : -1e30f;
    int img = i / NP;
    g_keys_in[i] = ((unsigned long long)(3 - img) << 32) | (unsigned long long)f2sortable(s);
    g_vals_in[i] = (unsigned int)(i % NP);
}

__global__ void k_gather(const float* __restrict__ loc,
                         const float* __restrict__ prior) {
    int t = blockIdx.x * blockDim.x + threadIdx.x;
    if (t >= NB * NSEL) return;
    int img = t / NSEL, j = t % NSEL;
    unsigned long long key = g_keys_out[img * NP + j];
    unsigned int p = g_vals_out[img * NP + j];
    g_sc[t] = sortable2f((unsigned int)key);

    const float* l  = loc   + ((size_t)img * NP + p) * 4;
    const float* pr = prior + (size_t)p * 4;
    float lx = l[0],  ly = l[1],  lw = l[2],  lh = l[3];
    float px = pr[0], py = pr[1], pw = pr[2], ph = pr[3];

    float cx = __fadd_rn(px, __fmul_rn(__fmul_rn(lx, 0.1f), pw));
    float cy = __fadd_rn(py, __fmul_rn(__fmul_rn(ly, 0.1f), ph));
    float w  = __fmul_rn(pw, expf(__fmul_rn(lw, 0.2f)));
    float h  = __fmul_rn(ph, expf(__fmul_rn(lh, 0.2f)));
    float x1 = __fsub_rn(cx, __fmul_rn(w, 0.5f));
    float y1 = __fsub_rn(cy, __fmul_rn(h, 0.5f));
    float x2 = __fadd_rn(x1, w);
    float y2 = __fadd_rn(y1, h);
    g_bx1[t] = x1; g_by1[t] = y1; g_bx2[t] = x2; g_by2[t] = y2;
}

// Upper-triangular tiled IoU bitmask (grid-wide, embarrassingly parallel).
// block = 64 threads (one row each); blockIdx = (col tile, row tile, image).
// Lower-triangle words of g_mask are never written (stay zero-initialized).
__global__ void k_mask() {
    int bx = blockIdx.x, by = blockIdx.y, img = blockIdx.z;
    if (bx < by) return;
    __shared__ float sx1[64], sy1[64], sx2[64], sy2[64], sa[64];
    int t  = threadIdx.x;
    int j0 = bx * 64;
    int jj = j0 + t;
    if (jj < NSEL) {
        int o = img * NSEL + jj;
        float x1 = g_bx1[o], y1 = g_by1[o], x2 = g_bx2[o], y2 = g_by2[o];
        sx1[t] = x1; sy1[t] = y1; sx2[t] = x2; sy2[t] = y2;
        sa[t] = __fmul_rn(__fsub_rn(x2, x1), __fsub_rn(y2, y1));
    }
    __syncthreads();
    int i = by * 64 + t;
    if (i >= NSEL) return;
    int oi = img * NSEL + i;
    float ix1 = g_bx1[oi], iy1 = g_by1[oi], ix2 = g_bx2[oi], iy2 = g_by2[oi];
    float ia  = __fmul_rn(__fsub_rn(ix2, ix1), __fsub_rn(iy2, iy1));
    int cnt = min(64, NSEL - j0);
    unsigned long long bits = 0ull;
#pragma unroll 4
    for (int c = 0; c < cnt; c++) {
        int j = j0 + c;
        if (j <= i) continue;
        float iw = fmaxf(__fsub_rn(fminf(ix2, sx2[c]), fmaxf(ix1, sx1[c])), 0.0f);
        float ih = fmaxf(__fsub_rn(fminf(iy2, sy2[c]), fmaxf(iy1, sy1[c])), 0.0f);
        float inter = __fmul_rn(iw, ih);
        float den   = __fsub_rn(__fadd_rn(ia, sa[c]), inter);
        float iou   = __fdiv_rn(inter, den);
        if (iou > NMS_T) bits |= (1ull << c);
    }
    g_mask[((size_t)img * NSEL + i) * NW + bx] = bits;
}

// One block (1024 threads) per image: 1024-wide chunked greedy over the
// precomputed bitmask with LAZY suppression — each chunk's 16 suppression
// words are built on demand from the global kept list (one parallel L2
// window), instead of eagerly updating all later words per chunk.
__global__ __launch_bounds__(RT, 1)
void k_reduce(float* __restrict__ out) {
    extern __shared__ unsigned long long rowm[];   // [CW * WPC], 128 KB
    __shared__ unsigned long long supp[WPC];
    __shared__ unsigned long long s_kept[WPC];
    __shared__ int keptlist[TOPK];                 // global candidate indices
    __shared__ int s_cnt;

    const int img = blockIdx.x;
    const int t   = threadIdx.x;
    const unsigned long long* mbase = g_mask + (size_t)img * NSEL * NW;

    // zero this image's two output pages (class 0 stays all-zero)
    float* page = out + (size_t)img * 2 * TOPK * 5;
    for (int i = t; i < 2 * TOPK * 5; i += RT) page[i] = 0.0f;

    int rank = 0;
    for (int c = 0; c < NCH; c++) {
        const int base = c * CW;
        const int w0   = c * WPC;
        const int i    = base + t;

        // (a) load this chunk's CW x WPC intra-chunk mask block (1 row/thread)
        if (i < NSEL) {
            const unsigned long long* rp = mbase + (size_t)i * NW + w0;
#pragma unroll
            for (int k = 0; k < WPC; k++)
                rowm[t * WPC + k] = (w0 + k < NW) ? rp[k] : 0ull;
        } else {
#pragma unroll
            for (int k = 0; k < WPC; k++) rowm[t * WPC + k] = 0ull;
        }
        if (t < WPC) supp[t] = 0ull;
        __syncthreads();

        // (b) mark tail (i >= NSEL) and below-threshold candidates dead
        {
            bool dd = (i >= NSEL) || !(g_sc[img * NSEL + min(i, NSEL - 1)] > CONF_T);
            unsigned bal = __ballot_sync(0xffffffffu, dd);
            if ((t & 31) == 0 && bal)
                atomicOr(&supp[t >> 6],
                         (unsigned long long)bal << (((t >> 5) & 1) * 32));
        }

        // (c) lazy suppression from earlier-chunk kept boxes:
        // thread (word w = t>>6, slice s = t&63) ORs mask[kept[k]][w0+w]
        {
            const int K = rank;
            const int w = t >> 6;        // 0..15
            const int s = t & 63;
            unsigned long long acc = 0ull;
            if (w0 + w < NW) {
                for (int k = s; k < K; k += 64)
                    acc |= mbase[(size_t)keptlist[k] * NW + w0 + w];
            }
#pragma unroll
            for (int off = 16; off; off >>= 1)
                acc |= __shfl_down_sync(0xffffffffu, acc, off);
            if ((t & 31) == 0 && acc) atomicOr(&supp[w], acc);
        }
        __syncthreads();

        // (d) sequential greedy on the 1024-bit availability vector (thread 0)
        if (t == 0) {
            unsigned long long av[WPC], kp[WPC];
#pragma unroll
            for (int k = 0; k < WPC; k++) { av[k] = ~supp[k]; kp[k] = 0ull; }
            int cnt = 0;
            const int room = TOPK - rank;
            while (cnt < room) {
                int ws = -1;
#pragma unroll
                for (int k = 0; k < WPC; k++)
                    if (ws < 0 && av[k]) ws = k;
                if (ws < 0) break;
                int b   = __ffsll((long long)av[ws]) - 1;
                int loc = ws * 64 + b;
                av[ws] &= ~(1ull << b);
                kp[ws] |= (1ull << b);
                keptlist[rank + cnt] = base + loc;
                cnt++;
                const unsigned long long* rr = &rowm[loc * WPC];
#pragma unroll
                for (int k = 0; k < WPC; k++) av[k] &= ~rr[k];
            }
#pragma unroll
            for (int k = 0; k < WPC; k++) s_kept[k] = kp[k];
            s_cnt = cnt;
        }
        __syncthreads();

        // (e) write output rows for newly-kept boxes (thread t owns local t)
        {
            const int wq = t >> 6, b = t & 63;
            if ((s_kept[wq] >> b) & 1ull) {
                int off = __popcll(s_kept[wq] & ((1ull << b) - 1ull));
#pragma unroll
                for (int k = 0; k < WPC; k++)
                    if (k < wq) off += __popcll(s_kept[k]);
                int o = img * NSEL + i;
                float* row = out + (((size_t)(img * 2 + 1)) * TOPK + rank + off) * 5;
                row[0] = g_sc[o];
                row[1] = g_bx1[o]; row[2] = g_by1[o];
                row[3] = g_bx2[o]; row[4] = g_by2[o];
            }
        }
        rank += s_cnt;
        if (rank >= TOPK) break;   // uniform
        __syncthreads();           // protect rowm/supp/keptlist for next chunk
    }
}

// ---------------- launch ------------------------------------------------------

extern "C" void kernel_launch(void* const* d_in, const int* in_sizes, int n_in,
                              void* d_out, int out_size) {
    const float* loc   = (const float*)d_in[0];
    const float* conf  = (const float*)d_in[1];
    const float* prior = (const float*)d_in[2];
    float* out = (float*)d_out;

    void *keys_in_p, *vals_in_p, *keys_out_p, *vals_out_p, *temp_p;
    cudaGetSymbolAddress(&keys_in_p,  g_keys_in);
    cudaGetSymbolAddress(&vals_in_p,  g_vals_in);
    cudaGetSymbolAddress(&keys_out_p, g_keys_out);
    cudaGetSymbolAddress(&vals_out_p, g_vals_out);
    cudaGetSymbolAddress(&temp_p,     g_temp);

    cudaFuncSetAttribute(k_reduce, cudaFuncAttributeMaxDynamicSharedMemorySize,
                         ROWM_BYTES);

    k_build<<<(NB * NP + 255) / 256, 256>>>(conf);

    size_t tmp_bytes = 0;
    cub::DeviceRadixSort::SortPairsDescending(
        nullptr, tmp_bytes,
        (const unsigned long long*)keys_in_p, (unsigned long long*)keys_out_p,
        (const unsigned int*)vals_in_p,       (unsigned int*)vals_out_p,
        NB * NP, 0, 34, (cudaStream_t)0);
    if (tmp_bytes > (size_t)(1u << 24)) tmp_bytes = (size_t)(1u << 24);
    cub::DeviceRadixSort::SortPairsDescending(
        temp_p, tmp_bytes,
        (const unsigned long long*)keys_in_p, (unsigned long long*)keys_out_p,
        (const unsigned int*)vals_in_p,       (unsigned int*)vals_out_p,
        NB * NP, 0, 34, (cudaStream_t)0);

    k_gather<<<(NB * NSEL + 255) / 256, 256>>>(loc, prior);

    dim3 mg(NW, NW, NB);
    k_mask<<<mg, 64>>>();

    k_reduce<<<NB, RT, ROWM_BYTES>>>(out);
}

// round 10
// speedup vs baseline: 1.3446x; 1.3446x over previous
#include <cuda_runtime.h>
#include <cub/cub.cuh>

// Defeat --use_fast_math's expf -> __expf macro so expf = accurate libdevice
// __nv_expf, matching XLA's f32 exp bit-for-bit.
#ifdef expf
#undef expf
#endif

#define NB      4        // batch
#define NP      34125    // priors
#define NSEL    5000     // NMS_TOP_K
#define TOPK    750
#define NW      79       // ceil(NSEL/64)
#define CONF_T  0.05f
#define NMS_T   0.3f
#define NT2     256      // reduce block threads
#define NCH     20       // ceil(NSEL/256) chunks of 256 candidates

// float bits of 0.05f; scores in (0.05,1) have bits in (OFFS, 0x3F800000)
#define OFFS    0x3D4CCCCDu

// ---------------- static device scratch (no allocations allowed) ------------
__device__ unsigned int g_keys_in [NB * NP];
__device__ unsigned int g_vals_in [NB * NP];
__device__ unsigned int g_keys_out[NB * NP];
__device__ unsigned int g_vals_out[NB * NP];

__device__ float g_bx1[NB * NSEL];
__device__ float g_by1[NB * NSEL];
__device__ float g_bx2[NB * NSEL];
__device__ float g_by2[NB * NSEL];
__device__ float g_sc [NB * NSEL];

__device__ unsigned long long g_mask[(size_t)NB * NSEL * NW]; // ~12.6 MB (L2-resident)
__device__ unsigned char     g_temp[1u << 24];                // cub temp, 16 MB

// ---------------- kernels ----------------------------------------------------

// 28-bit composite keys in a 32-bit sort: bits[26,28) = (3-img) so one
// descending onesweep run orders img 0 first; bits[0,26) = offset-compressed
// score bits (strictly monotone + injective on surviving scores; 0 = dead).
// Stable radix sort keeps ascending-index tie order == jax.lax.top_k.
__global__ void k_build(const float* __restrict__ conf) {
    int i = blockIdx.x * blockDim.x + threadIdx.x;
    if (i >= NB * NP) return;
    float c = conf[2 * i + 1];                 // class-1 score
    unsigned int b  = __float_as_uint(c);
    unsigned int cs = (c > CONF_T) ? (b - OFFS) : 0u;   // < 2^26
    int img = i / NP;
    g_keys_in[i] = ((unsigned int)(3 - img) << 26) | cs;
    g_vals_in[i] = (unsigned int)(i % NP);
}

__global__ void k_gather(const float* __restrict__ loc,
                         const float* __restrict__ prior) {
    int t = blockIdx.x * blockDim.x + threadIdx.x;
    if (t >= NB * NSEL) return;
    int img = t / NSEL, j = t % NSEL;
    unsigned int key = g_keys_out[img * NP + j];
    unsigned int cs  = key & 0x03FFFFFFu;
    unsigned int p   = g_vals_out[img * NP + j];
    g_sc[t] = cs ? __uint_as_float(cs + OFFS) : -1e30f;  // bit-exact recovery

    const float* l  = loc   + ((size_t)img * NP + p) * 4;
    const float* pr = prior + (size_t)p * 4;
    float lx = l[0],  ly = l[1],  lw = l[2],  lh = l[3];
    float px = pr[0], py = pr[1], pw = pr[2], ph = pr[3];

    float cx = __fadd_rn(px, __fmul_rn(__fmul_rn(lx, 0.1f), pw));
    float cy = __fadd_rn(py, __fmul_rn(__fmul_rn(ly, 0.1f), ph));
    float w  = __fmul_rn(pw, expf(__fmul_rn(lw, 0.2f)));
    float h  = __fmul_rn(ph, expf(__fmul_rn(lh, 0.2f)));
    float x1 = __fsub_rn(cx, __fmul_rn(w, 0.5f));
    float y1 = __fsub_rn(cy, __fmul_rn(h, 0.5f));
    float x2 = __fadd_rn(x1, w);
    float y2 = __fadd_rn(y1, h);
    g_bx1[t] = x1; g_by1[t] = y1; g_bx2[t] = x2; g_by2[t] = y2;
}

// Upper-triangular tiled IoU bitmask (grid-wide, embarrassingly parallel).
// block = 64 threads (one row each); blockIdx = (col tile, row tile, image).
__global__ void k_mask() {
    int bx = blockIdx.x, by = blockIdx.y, img = blockIdx.z;
    if (bx < by) return;   // lower-triangle words never consulted downstream
    __shared__ float sx1[64], sy1[64], sx2[64], sy2[64], sa[64];
    int t  = threadIdx.x;
    int j0 = bx * 64;
    int jj = j0 + t;
    if (jj < NSEL) {
        int o = img * NSEL + jj;
        float x1 = g_bx1[o], y1 = g_by1[o], x2 = g_bx2[o], y2 = g_by2[o];
        sx1[t] = x1; sy1[t] = y1; sx2[t] = x2; sy2[t] = y2;
        sa[t] = __fmul_rn(__fsub_rn(x2, x1), __fsub_rn(y2, y1));
    }
    __syncthreads();
    int i = by * 64 + t;
    if (i >= NSEL) return;
    int oi = img * NSEL + i;
    float ix1 = g_bx1[oi], iy1 = g_by1[oi], ix2 = g_bx2[oi], iy2 = g_by2[oi];
    float ia  = __fmul_rn(__fsub_rn(ix2, ix1), __fsub_rn(iy2, iy1));
    int cnt = min(64, NSEL - j0);
    unsigned long long bits = 0ull;
#pragma unroll 4
    for (int c = 0; c < cnt; c++) {
        int j = j0 + c;
        if (j <= i) continue;
        float iw = fmaxf(__fsub_rn(fminf(ix2, sx2[c]), fmaxf(ix1, sx1[c])), 0.0f);
        float ih = fmaxf(__fsub_rn(fminf(iy2, sy2[c]), fmaxf(iy1, sy1[c])), 0.0f);
        float inter = __fmul_rn(iw, ih);
        float den   = __fsub_rn(__fadd_rn(ia, sa[c]), inter);
        float iou   = __fdiv_rn(inter, den);
        if (iou > NMS_T) bits |= (1ull << c);
    }
    g_mask[((size_t)img * NSEL + i) * NW + bx] = bits;
}

// One block per image: 256-wide chunked greedy reduce over the precomputed
// bitmask. Eager suppression parallelized 4-threads-per-word; the shfl
// combine now runs a WARP-UNIFORM trip count (2 predicated iterations) so
// every lane reaches every __shfl_xor_sync (the round-9 hang).
__global__ __launch_bounds__(NT2, 1)
void k_reduce(float* __restrict__ out) {
    __shared__ unsigned long long remv[80];        // word 79 = pad
    __shared__ unsigned long long rowm[NT2 * 4];   // intra-chunk mask rows, 8KB
    __shared__ unsigned long long s_kept[4];
    __shared__ int s_cnt;
    __shared__ int keptlist[NT2];

    const int img = blockIdx.x;
    const int t   = threadIdx.x;
    const unsigned long long* mbase = g_mask + (size_t)img * NSEL * NW;

    // zero this image's two output pages (class 0 stays all-zero)
    float* page = out + (size_t)img * 2 * TOPK * 5;
    for (int i = t; i < 2 * TOPK * 5; i += NT2) page[i] = 0.0f;

    // suppression bitmap: tail bits (>= NSEL) preset; pad word = all-ones
    for (int w = t; w < 80; w += NT2) {
        unsigned long long m = 0ull;
        int b0 = w * 64;
        if (b0 + 64 > NSEL) {
            for (int b = 0; b < 64; b++)
                if (b0 + b >= NSEL) m |= (1ull << b);
        }
        remv[w] = m;
    }
    __syncthreads();
    // invalid candidates (score <= thresh): never kept, never suppress
    for (int j = t; j < NSEL; j += NT2)
        if (!(g_sc[img * NSEL + j] > CONF_T))
            atomicOr(&remv[j >> 6], 1ull << (j & 63));
    __syncthreads();

    int rank = 0;
    for (int c = 0; c < NCH; c++) {
        const int w0   = c * 4;
        const int base = c * 256;
        if ((remv[w0] & remv[w0 + 1] & remv[w0 + 2] & remv[w0 + 3]) == ~0ull)
            continue;   // uniform skip

        // (a) load the chunk's 256x4-word intra-chunk mask block
        {
            int i = base + t;
            if (i < NSEL) {
                const unsigned long long* rp = mbase + (size_t)i * NW + w0;
#pragma unroll
                for (int k = 0; k < 4; k++)
                    rowm[t * 4 + k] = (w0 + k < NW) ? rp[k] : 0ull;
            } else {
#pragma unroll
                for (int k = 0; k < 4; k++) rowm[t * 4 + k] = 0ull;
            }
        }
        __syncthreads();

        // (b) local greedy on a 256-bit avail vector, one thread, regs+LDS
        if (t == 0) {
            unsigned long long av[4], kp[4] = {0ull, 0ull, 0ull, 0ull};
#pragma unroll
            for (int k = 0; k < 4; k++) av[k] = ~remv[w0 + k];
            int cnt = 0, room = TOPK - rank;
            while (cnt < room) {
                int ws;
                if      (av[0]) ws = 0;
                else if (av[1]) ws = 1;
                else if (av[2]) ws = 2;
                else if (av[3]) ws = 3;
                else break;
                int b   = __ffsll((long long)av[ws]) - 1;
                int loc = ws * 64 + b;
                kp[ws] |= (1ull << b);
                keptlist[cnt++] = loc;
                av[0] &= ~rowm[loc * 4 + 0];
                av[1] &= ~rowm[loc * 4 + 1];
                av[2] &= ~rowm[loc * 4 + 2];
                av[3] &= ~rowm[loc * 4 + 3];
                av[ws] &= ~(1ull << b);
            }
            s_kept[0] = kp[0]; s_kept[1] = kp[1];
            s_kept[2] = kp[2]; s_kept[3] = kp[3];
            s_cnt = cnt;
        }
        __syncthreads();

        const int cnt = s_cnt;

        // (c) output rows for newly-kept boxes (thread t owns local row t)
        {
            int wq = t >> 6, b = t & 63;
            if ((s_kept[wq] >> b) & 1ull) {
                int off = 0;
#pragma unroll
                for (int k = 0; k < 4; k++)
                    if (k < wq) off += __popcll(s_kept[k]);
                off += __popcll(s_kept[wq] & ((1ull << b) - 1ull));
                int r = rank + off;
                int o = img * NSEL + base + t;
                float* row = out + (((size_t)(img * 2 + 1)) * TOPK + r) * 5;
                row[0] = g_sc[o];
                row[1] = g_bx1[o]; row[2] = g_by1[o];
                row[3] = g_bx2[o]; row[4] = g_by2[o];
            }
        }
        rank += cnt;
        if (rank >= TOPK) break;   // uniform

        // (d) suppress later chunks: 4 threads per word (group g = t>>2,
        // slice = t&3). WARP-UNIFORM 2-iteration loop (nwrem <= 75 < 128):
        // all lanes execute both shfl combines; loads/writes predicated.
        if (cnt > 0) {
            const int nwrem = NW - (w0 + 4);
#pragma unroll
            for (int it = 0; it < 2; it++) {
                const int g = (t >> 2) + it * 64;
                unsigned long long acc = 0ull;
                if (g < nwrem) {
                    const int w = w0 + 4 + g;
                    for (int k = (t & 3); k < cnt; k += 4)
                        acc |= mbase[(size_t)(base + keptlist[k]) * NW + w];
                }
                acc |= __shfl_xor_sync(0xffffffffu, acc, 1);
                acc |= __shfl_xor_sync(0xffffffffu, acc, 2);
                if ((t & 3) == 0 && g < nwrem) remv[w0 + 4 + g] |= acc;
            }
        }
        __syncthreads();
    }
}

// ---------------- launch ------------------------------------------------------

extern "C" void kernel_launch(void* const* d_in, const int* in_sizes, int n_in,
                              void* d_out, int out_size) {
    const float* loc   = (const float*)d_in[0];
    const float* conf  = (const float*)d_in[1];
    const float* prior = (const float*)d_in[2];
    float* out = (float*)d_out;

    void *keys_in_p, *vals_in_p, *keys_out_p, *vals_out_p, *temp_p;
    cudaGetSymbolAddress(&keys_in_p,  g_keys_in);
    cudaGetSymbolAddress(&vals_in_p,  g_vals_in);
    cudaGetSymbolAddress(&keys_out_p, g_keys_out);
    cudaGetSymbolAddress(&vals_out_p, g_vals_out);
    cudaGetSymbolAddress(&temp_p,     g_temp);

    k_build<<<(NB * NP + 255) / 256, 256>>>(conf);

    size_t tmp_bytes = 0;
    cub::DeviceRadixSort::SortPairsDescending(
        nullptr, tmp_bytes,
        (const unsigned int*)keys_in_p, (unsigned int*)keys_out_p,
        (const unsigned int*)vals_in_p, (unsigned int*)vals_out_p,
        NB * NP, 0, 28, (cudaStream_t)0);
    if (tmp_bytes > (size_t)(1u << 24)) tmp_bytes = (size_t)(1u << 24);
    cub::DeviceRadixSort::SortPairsDescending(
        temp_p, tmp_bytes,
        (const unsigned int*)keys_in_p, (unsigned int*)keys_out_p,
        (const unsigned int*)vals_in_p, (unsigned int*)vals_out_p,
        NB * NP, 0, 28, (cudaStream_t)0);

    k_gather<<<(NB * NSEL + 255) / 256, 256>>>(loc, prior);

    dim3 mg(NW, NW, NB);
    k_mask<<<mg, 64>>>();

    k_reduce<<<NB, NT2>>>(out);
}